// round 1
// baseline (speedup 1.0000x reference)
#include <cuda_runtime.h>
#include <math.h>

// Problem constants
#define Bc  4
#define Sc  2048
#define Dc  1024
#define Hc  16
#define DHc 64

// ---------------- device scratch (no allocations allowed) ----------------
__device__ float g_x  [(size_t)Bc*Sc*Dc];     // layernorm(inputs)
__device__ float g_pe [(size_t)Sc*Dc];        // sinusoidal PE
__device__ float g_q  [(size_t)Bc*Sc*Dc];
__device__ float g_k  [(size_t)Bc*Sc*Dc];
__device__ float g_v  [(size_t)Bc*Sc*Dc];
__device__ float g_p  [(size_t)Sc*Dc];        // pe @ Wpos
__device__ float g_sc [(size_t)Bc*Hc*Sc*Sc];  // content scores -> attn (in place)
__device__ float g_pos[(size_t)Bc*Hc*Sc*Sc];  // pos scores (pre-shift)
__device__ float g_ctx[(size_t)Bc*Sc*Dc];

// ---------------- LayerNorm: one block per row of 1024 ----------------
__global__ __launch_bounds__(256) void ln_kernel(
    const float* __restrict__ x, const float* __restrict__ gamma,
    const float* __restrict__ beta, float* __restrict__ out)
{
    int row = blockIdx.x;
    const float* xr = x + (size_t)row * Dc;
    float* orow = out + (size_t)row * Dc;
    int t = threadIdx.x;
    float4 v = *(const float4*)(xr + t * 4);

    __shared__ float red[256];
    float s = v.x + v.y + v.z + v.w;
    red[t] = s; __syncthreads();
    #pragma unroll
    for (int off = 128; off > 0; off >>= 1) {
        if (t < off) red[t] += red[t + off];
        __syncthreads();
    }
    float mu = red[0] * (1.0f / Dc);
    __syncthreads();

    float dx = v.x - mu, dy = v.y - mu, dz = v.z - mu, dw = v.w - mu;
    red[t] = dx*dx + dy*dy + dz*dz + dw*dw; __syncthreads();
    #pragma unroll
    for (int off = 128; off > 0; off >>= 1) {
        if (t < off) red[t] += red[t + off];
        __syncthreads();
    }
    float var = red[0] * (1.0f / Dc);
    float rstd = rsqrtf(var + 1e-5f);

    int c = t * 4;
    float4 o;
    o.x = dx * rstd * gamma[c+0] + beta[c+0];
    o.y = dy * rstd * gamma[c+1] + beta[c+1];
    o.z = dz * rstd * gamma[c+2] + beta[c+2];
    o.w = dw * rstd * gamma[c+3] + beta[c+3];
    *(float4*)(orow + c) = o;
}

// ---------------- Sinusoidal positional encoding ----------------
__global__ __launch_bounds__(256) void pe_kernel(float* __restrict__ pe)
{
    int s = blockIdx.x;
    for (int j = threadIdx.x; j < Dc / 2; j += blockDim.x) {
        float freq = expf(-(9.210340371976184f * (float)(2 * j) / (float)Dc));
        float ang = (float)s * freq;
        pe[(size_t)s * Dc + 2*j    ] = sinf(ang);
        pe[(size_t)s * Dc + 2*j + 1] = cosf(ang);
    }
}

// ---------------- Generic NN SGEMM: C = A[M,K] @ B[K,N] (+bias) ----------------
// z-batched: per-operand offset = (z/H)*sb + (z%H)*sh
template<int BM, int BN, int BK, int TM, int TN>
__global__ __launch_bounds__((BM/TM)*(BN/TN), 2) void sgemm_nn(
    const float* __restrict__ A, int lda, size_t Asb, size_t Ash,
    const float* __restrict__ Bw, int ldb, size_t Bsb, size_t Bsh,
    const float* __restrict__ bias,
    float* __restrict__ C, int ldc, size_t Csb, size_t Csh,
    int M, int N, int K)
{
    constexpr int THREADS = (BM/TM)*(BN/TN);
    __shared__ float As[BK][BM];
    __shared__ float Bs[BK][BN];

    int z = blockIdx.z;
    int zb = z / Hc, zh = z % Hc;
    A  += (size_t)zb * Asb + (size_t)zh * Ash;
    Bw += (size_t)zb * Bsb + (size_t)zh * Bsh;
    C  += (size_t)zb * Csb + (size_t)zh * Csh;

    int tid = threadIdx.x;
    int bx = blockIdx.x, by = blockIdx.y;
    int tx = tid % (BN / TN), ty = tid / (BN / TN);
    int row0 = by * BM, col0 = bx * BN;

    int arow = tid / (BK / 4);
    int acol = (tid % (BK / 4)) * 4;
    constexpr int B4 = BK * BN / 4;
    int brow = tid / (BN / 4);
    int bcol = (tid % (BN / 4)) * 4;

    float acc[TM][TN];
    #pragma unroll
    for (int i = 0; i < TM; i++)
        #pragma unroll
        for (int j = 0; j < TN; j++) acc[i][j] = 0.f;

    for (int k0 = 0; k0 < K; k0 += BK) {
        if (BM * BK / 4 == THREADS || tid < BM * BK / 4) {
            float4 av = *(const float4*)(A + (size_t)(row0 + arow) * lda + k0 + acol);
            As[acol+0][arow] = av.x; As[acol+1][arow] = av.y;
            As[acol+2][arow] = av.z; As[acol+3][arow] = av.w;
        }
        if (B4 == THREADS || tid < B4) {
            float4 bv = *(const float4*)(Bw + (size_t)(k0 + brow) * ldb + col0 + bcol);
            *(float4*)&Bs[brow][bcol] = bv;
        }
        __syncthreads();
        #pragma unroll
        for (int k = 0; k < BK; k++) {
            float a[TM], bfr[TN];
            #pragma unroll
            for (int i = 0; i < TM; i++) a[i] = As[k][ty * TM + i];
            #pragma unroll
            for (int j = 0; j < TN; j++) bfr[j] = Bs[k][tx * TN + j];
            #pragma unroll
            for (int i = 0; i < TM; i++)
                #pragma unroll
                for (int j = 0; j < TN; j++) acc[i][j] += a[i] * bfr[j];
        }
        __syncthreads();
    }

    #pragma unroll
    for (int i = 0; i < TM; i++) {
        int r = row0 + ty * TM + i;
        #pragma unroll
        for (int j = 0; j < TN; j++) {
            int c = col0 + tx * TN + j;
            float vv = acc[i][j];
            if (bias) vv += bias[c];
            C[(size_t)r * ldc + c] = vv;
        }
    }
}

// ---------------- NT score GEMM: C[s,t] = sum_d (A[s,d]+add[d]) * B[t,d] ----------------
// Per z = b*H+h:  A = Qbase + b*S*D + h*DH (lda=D), B = Bbase + b*Bzb + h*DH (ldb=D),
// C = Cbase + z*S*S (ldc=S).  M=N=S, K=DH.
__global__ __launch_bounds__(256, 2) void score_nt(
    const float* __restrict__ Qb, const float* __restrict__ addv,
    const float* __restrict__ Bb, size_t Bzb, float* __restrict__ Cb)
{
    __shared__ float As[8][128];
    __shared__ float Bs[8][128];

    int z = blockIdx.z;
    int b = z / Hc, h = z % Hc;
    const float* A  = Qb + (size_t)b * Sc * Dc + h * DHc;
    const float* Bm = Bb + (size_t)b * Bzb + h * DHc;
    float* C = Cb + (size_t)z * Sc * Sc;
    const float* addh = addv + h * DHc;

    int tid = threadIdx.x;
    int bx = blockIdx.x, by = blockIdx.y;
    int tx = tid % 16, ty = tid / 16;
    int lrow = tid / 2, lcol = (tid % 2) * 4;

    float acc[8][8];
    #pragma unroll
    for (int i = 0; i < 8; i++)
        #pragma unroll
        for (int j = 0; j < 8; j++) acc[i][j] = 0.f;

    for (int k0 = 0; k0 < DHc; k0 += 8) {
        float4 av = *(const float4*)(A + (size_t)(by * 128 + lrow) * Dc + k0 + lcol);
        float4 ad = *(const float4*)(addh + k0 + lcol);
        As[lcol+0][lrow] = av.x + ad.x; As[lcol+1][lrow] = av.y + ad.y;
        As[lcol+2][lrow] = av.z + ad.z; As[lcol+3][lrow] = av.w + ad.w;
        float4 bv = *(const float4*)(Bm + (size_t)(bx * 128 + lrow) * Dc + k0 + lcol);
        Bs[lcol+0][lrow] = bv.x; Bs[lcol+1][lrow] = bv.y;
        Bs[lcol+2][lrow] = bv.z; Bs[lcol+3][lrow] = bv.w;
        __syncthreads();
        #pragma unroll
        for (int k = 0; k < 8; k++) {
            float a[8], bf[8];
            #pragma unroll
            for (int i = 0; i < 8; i++) a[i] = As[k][ty * 8 + i];
            #pragma unroll
            for (int j = 0; j < 8; j++) bf[j] = Bs[k][tx * 8 + j];
            #pragma unroll
            for (int i = 0; i < 8; i++)
                #pragma unroll
                for (int j = 0; j < 8; j++) acc[i][j] += a[i] * bf[j];
        }
        __syncthreads();
    }

    #pragma unroll
    for (int i = 0; i < 8; i++) {
        int r = by * 128 + ty * 8 + i;
        #pragma unroll
        for (int j = 0; j < 8; j++) {
            C[(size_t)r * Sc + bx * 128 + tx * 8 + j] = acc[i][j];
        }
    }
}

// ---------------- Fused rel-shift + scale + softmax (in place on g_sc) --------------
// shifted[r,c] = pos[r, c-r+S-1]  (c<=r);  0 (c==r+1);  pos[r+1, c-r-2]  (c>=r+2)
__global__ __launch_bounds__(256) void softmax_shift(
    float* __restrict__ scb, const float* __restrict__ posb)
{
    int r = blockIdx.x;
    int z = blockIdx.y;
    float* crow = scb + ((size_t)z * Sc + r) * Sc;
    const float* p0 = posb + ((size_t)z * Sc + r) * Sc;
    const float* p1 = p0 + Sc;   // only read when c >= r+2 (implies r+1 <= S-1)
    int t = threadIdx.x;

    float vals[8];
    float mx = -3.4e38f;
    #pragma unroll
    for (int i = 0; i < 8; i++) {
        int c = t + i * 256;
        float pv;
        if (c <= r)          pv = p0[c - r + Sc - 1];
        else if (c == r + 1) pv = 0.f;
        else                 pv = p1[c - r - 2];
        float v = (crow[c] + pv) * 0.03125f;   // 1/sqrt(1024)
        vals[i] = v;
        mx = fmaxf(mx, v);
    }

    __shared__ float red[256];
    red[t] = mx; __syncthreads();
    #pragma unroll
    for (int off = 128; off > 0; off >>= 1) {
        if (t < off) red[t] = fmaxf(red[t], red[t + off]);
        __syncthreads();
    }
    mx = red[0]; __syncthreads();

    float s = 0.f;
    #pragma unroll
    for (int i = 0; i < 8; i++) { vals[i] = __expf(vals[i] - mx); s += vals[i]; }
    red[t] = s; __syncthreads();
    #pragma unroll
    for (int off = 128; off > 0; off >>= 1) {
        if (t < off) red[t] += red[t + off];
        __syncthreads();
    }
    float rs = 1.0f / red[0];
    #pragma unroll
    for (int i = 0; i < 8; i++) crow[t + i * 256] = vals[i] * rs;
}

// ---------------- host launch ----------------
extern "C" void kernel_launch(void* const* d_in, const int* in_sizes, int n_in,
                              void* d_out, int out_size)
{
    const float* inputs    = (const float*)d_in[0];
    const float* pre_block = (const float*)d_in[1];
    const float* ln_gamma  = (const float*)d_in[2];
    const float* ln_beta   = (const float*)d_in[3];
    const float* Wq        = (const float*)d_in[4];
    const float* bq        = (const float*)d_in[5];
    const float* Wk        = (const float*)d_in[6];
    const float* bk        = (const float*)d_in[7];
    const float* Wv        = (const float*)d_in[8];
    const float* bv        = (const float*)d_in[9];
    const float* Wpos      = (const float*)d_in[10];
    const float* u_bias    = (const float*)d_in[11];
    const float* v_bias    = (const float*)d_in[12];
    const float* Wo        = (const float*)d_in[13];
    const float* bo        = (const float*)d_in[14];
    float* out = (float*)d_out;

    float *x, *pe, *q, *k, *v, *p, *sc, *pos, *ctx;
    cudaGetSymbolAddress((void**)&x,   g_x);
    cudaGetSymbolAddress((void**)&pe,  g_pe);
    cudaGetSymbolAddress((void**)&q,   g_q);
    cudaGetSymbolAddress((void**)&k,   g_k);
    cudaGetSymbolAddress((void**)&v,   g_v);
    cudaGetSymbolAddress((void**)&p,   g_p);
    cudaGetSymbolAddress((void**)&sc,  g_sc);
    cudaGetSymbolAddress((void**)&pos, g_pos);
    cudaGetSymbolAddress((void**)&ctx, g_ctx);

    // 1) LayerNorm + PE
    ln_kernel<<<Bc * Sc, 256>>>(inputs, ln_gamma, ln_beta, x);
    pe_kernel<<<Sc, 256>>>(pe);

    // 2) Projections
    dim3 gQ(Dc / 128, (Bc * Sc) / 128, 1);
    sgemm_nn<128,128,8,8,8><<<gQ, 256>>>(x, Dc, 0, 0, Wq, Dc, 0, 0, bq,
                                         q, Dc, 0, 0, Bc * Sc, Dc, Dc);
    sgemm_nn<128,128,8,8,8><<<gQ, 256>>>(x, Dc, 0, 0, Wk, Dc, 0, 0, bk,
                                         k, Dc, 0, 0, Bc * Sc, Dc, Dc);
    sgemm_nn<128,128,8,8,8><<<gQ, 256>>>(pre_block, Dc, 0, 0, Wv, Dc, 0, 0, bv,
                                         v, Dc, 0, 0, Bc * Sc, Dc, Dc);
    dim3 gP(Dc / 128, Sc / 128, 1);
    sgemm_nn<128,128,8,8,8><<<gP, 256>>>(pe, Dc, 0, 0, Wpos, Dc, 0, 0, nullptr,
                                         p, Dc, 0, 0, Sc, Dc, Dc);

    // 3) Content & positional score GEMMs (K = 64, NT)
    dim3 gS(Sc / 128, Sc / 128, Bc * Hc);
    score_nt<<<gS, 256>>>(q, u_bias, k, (size_t)Sc * Dc, sc);
    score_nt<<<gS, 256>>>(q, v_bias, p, (size_t)0,       pos);

    // 4) rel-shift + scale + softmax (attn written in place to g_sc)
    dim3 gSm(Sc, Bc * Hc);
    softmax_shift<<<gSm, 256>>>(sc, pos);

    // 5) ctx = attn @ V  (M=S, N=DH, K=S per (b,h))
    dim3 gC(1, Sc / 128, Bc * Hc);
    sgemm_nn<128,64,8,8,4><<<gC, 256>>>(
        sc,  Sc, (size_t)Hc * Sc * Sc, (size_t)Sc * Sc,
        v,   Dc, (size_t)Sc * Dc,      (size_t)DHc,
        nullptr,
        ctx, Dc, (size_t)Sc * Dc,      (size_t)DHc,
        Sc, DHc, Sc);

    // 6) out = ctx @ Wo + bo
    dim3 gO(Dc / 128, (Bc * Sc) / 128, 1);
    sgemm_nn<128,128,8,8,8><<<gO, 256>>>(ctx, Dc, 0, 0, Wo, Dc, 0, 0, bo,
                                         out, Dc, 0, 0, Bc * Sc, Dc, Dc);
}

// round 3
// speedup vs baseline: 4.0274x; 4.0274x over previous
#include <cuda_runtime.h>
#include <cuda_fp16.h>
#include <math.h>
#include <stdint.h>

#define Bc  4
#define Sc  2048
#define Dc  1024
#define Hc  16
#define DHc 64

__device__ __half g_xh  [(size_t)Bc*Sc*Dc];
__device__ __half g_peh [(size_t)Sc*Dc];
__device__ __half g_preh[(size_t)Bc*Sc*Dc];
__device__ __half g_qh  [(size_t)Bc*Sc*Dc];
__device__ __half g_kh  [(size_t)Bc*Sc*Dc];
__device__ __half g_vh  [(size_t)Bc*Sc*Dc];
__device__ __half g_vth [(size_t)Bc*Sc*Dc];
__device__ __half g_ph  [(size_t)Sc*Dc];
__device__ __half g_ctxh[(size_t)Bc*Sc*Dc];
__device__ __half g_wtq [(size_t)Dc*Dc];
__device__ __half g_wtk [(size_t)Dc*Dc];
__device__ __half g_wtv [(size_t)Dc*Dc];
__device__ __half g_wtp [(size_t)Dc*Dc];
__device__ __half g_wto [(size_t)Dc*Dc];
__device__ __half g_uh  [Hc*DHc];
__device__ __half g_vbh [Hc*DHc];
__device__ __half g_sch [(size_t)Bc*Hc*Sc*Sc];
__device__ __half g_posh[(size_t)Bc*Hc*Sc*Sc];

__device__ __forceinline__ uint32_t smem_u32(const void* p) {
    uint32_t a;
    asm("{ .reg .u64 t; cvta.to.shared.u64 t, %1; cvt.u32.u64 %0, t; }"
        : "=r"(a) : "l"(p));
    return a;
}
__device__ __forceinline__ void ldsm_x4(uint32_t& r0, uint32_t& r1,
                                        uint32_t& r2, uint32_t& r3, uint32_t a) {
    asm volatile("ldmatrix.sync.aligned.m8n8.x4.shared.b16 {%0,%1,%2,%3}, [%4];"
                 : "=r"(r0), "=r"(r1), "=r"(r2), "=r"(r3) : "r"(a));
}
__device__ __forceinline__ void mma16816(float* d, const uint32_t* a, const uint32_t* b) {
    asm volatile("mma.sync.aligned.m16n8k16.row.col.f32.f16.f16.f32 "
                 "{%0,%1,%2,%3},{%4,%5,%6,%7},{%8,%9},{%0,%1,%2,%3};"
                 : "+f"(d[0]), "+f"(d[1]), "+f"(d[2]), "+f"(d[3])
                 : "r"(a[0]), "r"(a[1]), "r"(a[2]), "r"(a[3]), "r"(b[0]), "r"(b[1]));
}

template<int BN, int MW, int NW, bool OUT_HALF>
__global__ __launch_bounds__(256, 2) void gemm_mma(
    const __half* __restrict__ A, int lda, size_t Asb, size_t Ash,
    const __half* __restrict__ addA,
    const __half* __restrict__ B, int ldb, size_t Bsb, size_t Bsh,
    const float* __restrict__ bias,
    void* __restrict__ Cv, int ldc, size_t Csb, size_t Csh, int K)
{
    constexpr int BM = 128, BK = 32, LDS = BK + 8;
    constexpr int WM = BM / MW, WN = BN / NW;
    constexpr int MI = WM / 16, NI = WN / 8;
    constexpr int AU = BM * BK / 8 / 256;
    constexpr int BU = BN * BK / 8 / 256;

    __shared__ __half sA[2][BM * LDS];
    __shared__ __half sB[2][BN * LDS];

    const int tid = threadIdx.x;
    const int wid = tid >> 5, lane = tid & 31;
    const int z = blockIdx.z, zb = z / Hc, zh = z % Hc;
    A += (size_t)zb * Asb + (size_t)zh * Ash;
    B += (size_t)zb * Bsb + (size_t)zh * Bsh;
    if (addA) addA += (size_t)zh * DHc;
    const int row0 = blockIdx.y * BM, col0 = blockIdx.x * BN;
    const int wm = (wid / NW) * WM, wn = (wid % NW) * WN;

    float acc[MI][NI][4];
    #pragma unroll
    for (int i = 0; i < MI; i++)
        #pragma unroll
        for (int j = 0; j < NI; j++)
            #pragma unroll
            for (int q = 0; q < 4; q++) acc[i][j][q] = 0.f;

    uint4 ra[AU], rb[BU];
    auto load_g = [&](int k0) {
        #pragma unroll
        for (int u = 0; u < AU; u++) {
            int unit = tid + u * 256;
            int rr = unit >> 2, cc = unit & 3;
            uint4 v = *(const uint4*)(const void*)(A + (size_t)(row0 + rr) * lda + k0 + cc * 8);
            if (addA) {
                uint4 ad = *(const uint4*)(const void*)(addA + k0 + cc * 8);
                __half2* vp = (__half2*)&v;
                const __half2* ap = (const __half2*)&ad;
                vp[0] = __hadd2(vp[0], ap[0]); vp[1] = __hadd2(vp[1], ap[1]);
                vp[2] = __hadd2(vp[2], ap[2]); vp[3] = __hadd2(vp[3], ap[3]);
            }
            ra[u] = v;
        }
        #pragma unroll
        for (int u = 0; u < BU; u++) {
            int unit = tid + u * 256;
            int rr = unit >> 2, cc = unit & 3;
            rb[u] = *(const uint4*)(const void*)(B + (size_t)(col0 + rr) * ldb + k0 + cc * 8);
        }
    };
    auto store_s = [&](int buf) {
        #pragma unroll
        for (int u = 0; u < AU; u++) {
            int unit = tid + u * 256;
            int rr = unit >> 2, cc = unit & 3;
            *(uint4*)(void*)&sA[buf][rr * LDS + cc * 8] = ra[u];
        }
        #pragma unroll
        for (int u = 0; u < BU; u++) {
            int unit = tid + u * 256;
            int rr = unit >> 2, cc = unit & 3;
            *(uint4*)(void*)&sB[buf][rr * LDS + cc * 8] = rb[u];
        }
    };

    const uint32_t sAb[2] = { smem_u32(sA[0]), smem_u32(sA[1]) };
    const uint32_t sBb[2] = { smem_u32(sB[0]), smem_u32(sB[1]) };

    load_g(0);
    store_s(0);
    __syncthreads();

    const int nch = K >> 5;
    for (int ch = 0; ch < nch; ch++) {
        if (ch + 1 < nch) load_g((ch + 1) << 5);
        const int buf = ch & 1;
        #pragma unroll
        for (int kk = 0; kk < 2; kk++) {
            uint32_t af[MI][4], bf[NI][2];
            #pragma unroll
            for (int mi = 0; mi < MI; mi++) {
                uint32_t addr = sAb[buf] +
                    ((wm + mi * 16 + (lane & 15)) * LDS + kk * 16 + (lane >> 4) * 8) * 2;
                ldsm_x4(af[mi][0], af[mi][1], af[mi][2], af[mi][3], addr);
            }
            #pragma unroll
            for (int n2 = 0; n2 < NI / 2; n2++) {
                int nr = wn + n2 * 16 + (lane & 7) + ((lane & 16) ? 8 : 0);
                int ko = (lane & 8) ? 8 : 0;
                uint32_t addr = sBb[buf] + (nr * LDS + kk * 16 + ko) * 2;
                ldsm_x4(bf[2*n2][0], bf[2*n2][1], bf[2*n2+1][0], bf[2*n2+1][1], addr);
            }
            #pragma unroll
            for (int mi = 0; mi < MI; mi++)
                #pragma unroll
                for (int ni = 0; ni < NI; ni++)
                    mma16816(acc[mi][ni], af[mi], bf[ni]);
        }
        if (ch + 1 < nch) {
            store_s(1 - buf);
            __syncthreads();
        }
    }

    const int g = lane >> 2, t2 = (lane & 3) * 2;
    #pragma unroll
    for (int mi = 0; mi < MI; mi++) {
        #pragma unroll
        for (int hf = 0; hf < 2; hf++) {
            int r = row0 + wm + mi * 16 + g + hf * 8;
            #pragma unroll
            for (int ni = 0; ni < NI; ni++) {
                int c = col0 + wn + ni * 8 + t2;
                float v0 = acc[mi][ni][hf * 2 + 0];
                float v1 = acc[mi][ni][hf * 2 + 1];
                if (bias) { v0 += bias[c]; v1 += bias[c + 1]; }
                if (OUT_HALF) {
                    __half* Ch = (__half*)Cv + (size_t)zb * Csb + (size_t)zh * Csh;
                    *(__half2*)(void*)(Ch + (size_t)r * ldc + c) = __floats2half2_rn(v0, v1);
                } else {
                    float* Cf = (float*)Cv + (size_t)zb * Csb + (size_t)zh * Csh;
                    float2 f; f.x = v0; f.y = v1;
                    *(float2*)(void*)(Cf + (size_t)r * ldc + c) = f;
                }
            }
        }
    }
}

__global__ __launch_bounds__(256) void ln_kernel(
    const float* __restrict__ x, const float* __restrict__ gamma,
    const float* __restrict__ beta, __half* __restrict__ out)
{
    int row = blockIdx.x;
    const float* xr = x + (size_t)row * Dc;
    __half* orow = out + (size_t)row * Dc;
    int t = threadIdx.x;
    float4 v = *(const float4*)(xr + t * 4);

    __shared__ float red[256];
    red[t] = v.x + v.y + v.z + v.w; __syncthreads();
    #pragma unroll
    for (int off = 128; off > 0; off >>= 1) {
        if (t < off) red[t] += red[t + off];
        __syncthreads();
    }
    float mu = red[0] * (1.0f / Dc);
    __syncthreads();
    float dx = v.x - mu, dy = v.y - mu, dz = v.z - mu, dw = v.w - mu;
    red[t] = dx*dx + dy*dy + dz*dz + dw*dw; __syncthreads();
    #pragma unroll
    for (int off = 128; off > 0; off >>= 1) {
        if (t < off) red[t] += red[t + off];
        __syncthreads();
    }
    float rstd = rsqrtf(red[0] * (1.0f / Dc) + 1e-5f);
    int c = t * 4;
    float o0 = dx * rstd * gamma[c+0] + beta[c+0];
    float o1 = dy * rstd * gamma[c+1] + beta[c+1];
    float o2 = dz * rstd * gamma[c+2] + beta[c+2];
    float o3 = dw * rstd * gamma[c+3] + beta[c+3];
    ((__half2*)(orow + c))[0] = __floats2half2_rn(o0, o1);
    ((__half2*)(orow + c))[1] = __floats2half2_rn(o2, o3);
}

__global__ __launch_bounds__(256) void pe_kernel(__half* __restrict__ pe)
{
    int s = blockIdx.x;
    for (int j = threadIdx.x; j < Dc / 2; j += blockDim.x) {
        float freq = expf(-(9.210340371976184f * (float)(2 * j) / (float)Dc));
        float ang = (float)s * freq;
        pe[(size_t)s * Dc + 2*j    ] = __float2half_rn(sinf(ang));
        pe[(size_t)s * Dc + 2*j + 1] = __float2half_rn(cosf(ang));
    }
}

__global__ __launch_bounds__(256) void conv_f2h(const float* __restrict__ in,
                                                __half* __restrict__ out)
{
    size_t i = ((size_t)blockIdx.x * 256 + threadIdx.x) * 4;
    float4 a = *(const float4*)(in + i);
    ((__half2*)(out + i))[0] = __floats2half2_rn(a.x, a.y);
    ((__half2*)(out + i))[1] = __floats2half2_rn(a.z, a.w);
}

__global__ __launch_bounds__(256) void wtrans(const float* __restrict__ W,
                                              __half* __restrict__ Wt)
{
    __shared__ float tile[32][33];
    int n0 = blockIdx.x * 32, k0 = blockIdx.y * 32;
    int x = threadIdx.x, y = threadIdx.y;
    #pragma unroll
    for (int m = 0; m < 4; m++)
        tile[y + 8*m][x] = W[(size_t)(k0 + y + 8*m) * Dc + n0 + x];
    __syncthreads();
    #pragma unroll
    for (int m = 0; m < 4; m++)
        Wt[(size_t)(n0 + y + 8*m) * Dc + k0 + x] = __float2half_rn(tile[x][y + 8*m]);
}

__global__ __launch_bounds__(256) void vtrans(const __half* __restrict__ v,
                                              __half* __restrict__ vt)
{
    __shared__ __half tile[32][33];
    int zz = blockIdx.z;
    int bb = zz / Hc, h = zz % Hc;
    int s0 = blockIdx.x * 32, d0 = blockIdx.y * 32;
    int x = threadIdx.x, y = threadIdx.y;
    const __half* src = v + (size_t)bb * Sc * Dc + h * DHc;
    #pragma unroll
    for (int m = 0; m < 4; m++)
        tile[y + 8*m][x] = src[(size_t)(s0 + y + 8*m) * Dc + d0 + x];
    __syncthreads();
    __half* dst = vt + (size_t)zz * DHc * Sc;
    #pragma unroll
    for (int m = 0; m < 4; m++)
        dst[(size_t)(d0 + y + 8*m) * Sc + s0 + x] = tile[x][y + 8*m];
}

__global__ __launch_bounds__(256) void softmax_shift(
    __half* __restrict__ scb, const __half* __restrict__ posb)
{
    int r = blockIdx.x;
    int z = blockIdx.y;
    __half* crow = scb + ((size_t)z * Sc + r) * Sc;
    const __half* p0 = posb + ((size_t)z * Sc + r) * Sc;
    const __half* p1 = p0 + Sc;
    int t = threadIdx.x;

    float vals[8];
    float mx = -3.4e38f;
    #pragma unroll
    for (int i = 0; i < 8; i++) {
        int c = t + i * 256;
        float pv;
        if (c <= r)          pv = __half2float(p0[c - r + Sc - 1]);
        else if (c == r + 1) pv = 0.f;
        else                 pv = __half2float(p1[c - r - 2]);
        float v = (__half2float(crow[c]) + pv) * 0.03125f;
        vals[i] = v;
        mx = fmaxf(mx, v);
    }

    __shared__ float red[256];
    red[t] = mx; __syncthreads();
    #pragma unroll
    for (int off = 128; off > 0; off >>= 1) {
        if (t < off) red[t] = fmaxf(red[t], red[t + off]);
        __syncthreads();
    }
    mx = red[0]; __syncthreads();

    float s = 0.f;
    #pragma unroll
    for (int i = 0; i < 8; i++) { vals[i] = __expf(vals[i] - mx); s += vals[i]; }
    red[t] = s; __syncthreads();
    #pragma unroll
    for (int off = 128; off > 0; off >>= 1) {
        if (t < off) red[t] += red[t + off];
        __syncthreads();
    }
    float rs = 1.0f / red[0];
    #pragma unroll
    for (int i = 0; i < 8; i++)
        crow[t + i * 256] = __float2half_rn(vals[i] * rs);
}

extern "C" void kernel_launch(void* const* d_in, const int* in_sizes, int n_in,
                              void* d_out, int out_size)
{
    const float* inputs    = (const float*)d_in[0];
    const float* pre_block = (const float*)d_in[1];
    const float* ln_gamma  = (const float*)d_in[2];
    const float* ln_beta   = (const float*)d_in[3];
    const float* Wq        = (const float*)d_in[4];
    const float* bq        = (const float*)d_in[5];
    const float* Wk        = (const float*)d_in[6];
    const float* bk        = (const float*)d_in[7];
    const float* Wv        = (const float*)d_in[8];
    const float* bv        = (const float*)d_in[9];
    const float* Wpos      = (const float*)d_in[10];
    const float* u_bias    = (const float*)d_in[11];
    const float* v_bias    = (const float*)d_in[12];
    const float* Wo        = (const float*)d_in[13];
    const float* bo        = (const float*)d_in[14];
    float* out = (float*)d_out;

    __half *xh, *peh, *preh, *qh, *kh, *vh, *vth, *ph, *ctxh;
    __half *wtq, *wtk, *wtv, *wtp, *wto, *uh, *vbh, *sch, *posh;
    cudaGetSymbolAddress((void**)&xh,   g_xh);
    cudaGetSymbolAddress((void**)&peh,  g_peh);
    cudaGetSymbolAddress((void**)&preh, g_preh);
    cudaGetSymbolAddress((void**)&qh,   g_qh);
    cudaGetSymbolAddress((void**)&kh,   g_kh);
    cudaGetSymbolAddress((void**)&vh,   g_vh);
    cudaGetSymbolAddress((void**)&vth,  g_vth);
    cudaGetSymbolAddress((void**)&ph,   g_ph);
    cudaGetSymbolAddress((void**)&ctxh, g_ctxh);
    cudaGetSymbolAddress((void**)&wtq,  g_wtq);
    cudaGetSymbolAddress((void**)&wtk,  g_wtk);
    cudaGetSymbolAddress((void**)&wtv,  g_wtv);
    cudaGetSymbolAddress((void**)&wtp,  g_wtp);
    cudaGetSymbolAddress((void**)&wto,  g_wto);
    cudaGetSymbolAddress((void**)&uh,   g_uh);
    cudaGetSymbolAddress((void**)&vbh,  g_vbh);
    cudaGetSymbolAddress((void**)&sch,  g_sch);
    cudaGetSymbolAddress((void**)&posh, g_posh);

    const size_t SD = (size_t)Sc * Dc;
    const size_t SS = (size_t)Sc * Sc;

    ln_kernel<<<Bc * Sc, 256>>>(inputs, ln_gamma, ln_beta, xh);
    pe_kernel<<<Sc, 256>>>(peh);
    conv_f2h<<<(Bc * Sc * Dc) / 1024, 256>>>(pre_block, preh);
    conv_f2h<<<1, 256>>>(u_bias, uh);
    conv_f2h<<<1, 256>>>(v_bias, vbh);
    dim3 wt(Dc / 32, Dc / 32), wb(32, 8);
    wtrans<<<wt, wb>>>(Wq, wtq);
    wtrans<<<wt, wb>>>(Wk, wtk);
    wtrans<<<wt, wb>>>(Wv, wtv);
    wtrans<<<wt, wb>>>(Wpos, wtp);
    wtrans<<<wt, wb>>>(Wo, wto);

    dim3 gQ(Dc / 128, (Bc * Sc) / 128, 1);
    gemm_mma<128, 2, 4, true><<<gQ, 256>>>(xh, Dc, 0, 0, nullptr, wtq, Dc, 0, 0,
                                           bq, qh, Dc, 0, 0, Dc);
    gemm_mma<128, 2, 4, true><<<gQ, 256>>>(xh, Dc, 0, 0, nullptr, wtk, Dc, 0, 0,
                                           bk, kh, Dc, 0, 0, Dc);
    gemm_mma<128, 2, 4, true><<<gQ, 256>>>(preh, Dc, 0, 0, nullptr, wtv, Dc, 0, 0,
                                           bv, vh, Dc, 0, 0, Dc);
    dim3 gP(Dc / 128, Sc / 128, 1);
    gemm_mma<128, 2, 4, true><<<gP, 256>>>(peh, Dc, 0, 0, nullptr, wtp, Dc, 0, 0,
                                           nullptr, ph, Dc, 0, 0, Dc);

    vtrans<<<dim3(Sc / 32, DHc / 32, Bc * Hc), wb>>>(vh, vth);

    dim3 gS(Sc / 128, Sc / 128, Bc * Hc);
    gemm_mma<128, 2, 4, true><<<gS, 256>>>(qh, Dc, SD, DHc, uh,
                                           kh, Dc, SD, DHc, nullptr,
                                           sch, Sc, (size_t)Hc * SS, SS, DHc);
    gemm_mma<128, 2, 4, true><<<gS, 256>>>(qh, Dc, SD, DHc, vbh,
                                           ph, Dc, 0, DHc, nullptr,
                                           posh, Sc, (size_t)Hc * SS, SS, DHc);

    softmax_shift<<<dim3(Sc, Bc * Hc), 256>>>(sch, posh);

    dim3 gC(1, Sc / 128, Bc * Hc);
    gemm_mma<64, 4, 2, true><<<gC, 256>>>(sch, Sc, (size_t)Hc * SS, SS, nullptr,
                                          vth, Sc, SD, (size_t)DHc * Sc, nullptr,
                                          ctxh, Dc, SD, DHc, Sc);

    dim3 gO(Dc / 128, (Bc * Sc) / 128, 1);
    gemm_mma<128, 2, 4, false><<<gO, 256>>>(ctxh, Dc, 0, 0, nullptr, wto, Dc, 0, 0,
                                            bo, out, Dc, 0, 0, Dc);
}